// round 2
// baseline (speedup 1.0000x reference)
#include <cuda_runtime.h>

#define NB 16
#define NCI 64
#define NCO 128
#define NH 512
#define NW 64
#define CEPS 1e-5f
#define NHW_F 524288.0f   // NB*NH*NW per-channel count

// ---------------- scratch (device globals; no allocations allowed) ----------
__device__ float g_hraw[(size_t)NB * NCO * NH * NW];   // raw conv output, 268MB
__device__ float g_xm[NB * NCO * NH];                  // row means of post-BN1-ReLU
__device__ float g_xn[NB * NCO * NH];                  // layernormed
__device__ float g_f[(size_t)NB * NH * NH];            // softmax(attention)
__device__ float g_zz[NB * NCO * NH];                  // z = Wc @ xn + bc
__device__ float g_y3[NB * NCO * NH];                  // final NL branch
__device__ float g_p1[NB * NCO];                       // per-(b,c) sum of hpost
__device__ float g_p2[NB * NCO];                       // per-(b,c) sum of hpost^2
__device__ float g_s1[NCO];                            // per-channel raw conv sums
__device__ float g_s2[NCO];
__device__ float g_a1[NCO], g_b1v[NCO];                // BN1 scale/shift
__device__ float g_a2[NCO], g_b2v[NCO];                // BN2 scale/shift
__device__ float g_wct[NCO * NCO];                     // (out_w@g_w) transposed [c][o]
__device__ float g_bcv[NCO];                           // out_w@g_b

__device__ __forceinline__ float warpsum(float v) {
#pragma unroll
    for (int o = 16; o; o >>= 1) v += __shfl_down_sync(0xffffffffu, v, o);
    return v;
}
__device__ __forceinline__ float warpmax(float v) {
#pragma unroll
    for (int o = 16; o; o >>= 1) v = fmaxf(v, __shfl_xor_sync(0xffffffffu, v, o));
    return v;
}

// ---------------- 0: zero the atomic accumulators ---------------------------
__global__ void k_zero() {
    int t = threadIdx.x;
    if (t < NCO) { g_s1[t] = 0.f; g_s2[t] = 0.f; }
}

// ---------------- 1: conv 3x3 reflect, raw output + per-channel stats -------
// grid: 8192 blocks = (b,h). block: 256 threads.
// thread: 4 w (w0..w0+3) x 8 couts. smem: x rows [3][8][68], weights [8][9][140-pad]
__global__ void __launch_bounds__(256) k_conv(const float* __restrict__ x,
                                              const float* __restrict__ cw) {
    __shared__ float sx[3 * 8 * 68];     // [kh][cin][wi], wi in 0..65 valid
    __shared__ float sw[8 * 1260];       // [cin][k(stride140)][cout]

    int bx = blockIdx.x;
    int b = bx >> 9, h = bx & 511;
    int t = threadIdx.x;
    int w0 = (t & 15) * 4;
    int co8 = (t >> 4) * 8;

    float acc[8][4];
#pragma unroll
    for (int i = 0; i < 8; i++)
#pragma unroll
        for (int j = 0; j < 4; j++) acc[i][j] = 0.f;

    int hm = (h == 0) ? 1 : h - 1;
    int hp = (h == NH - 1) ? NH - 2 : h + 1;
    const float* xb = x + (size_t)b * NCI * NH * NW;

    for (int ch = 0; ch < 8; ++ch) {
        int ci0 = ch * 8;
        // load x tile: 3 rows x 8 cins x 66 (reflect-padded in W)
        for (int i = t; i < 1584; i += 256) {
            int kh = i / 528;
            int rem = i - kh * 528;
            int ci = rem / 66;
            int wi = rem - ci * 66;
            int ws = wi - 1;
            if (ws < 0) ws = 1; else if (ws > 63) ws = 62;
            int row = (kh == 0) ? hm : ((kh == 1) ? h : hp);
            sx[kh * 544 + ci * 68 + wi] =
                xb[(size_t)(ci0 + ci) * (NH * NW) + row * NW + ws];
        }
        // load weights: conv_w[cout][cin][kh][kw] -> sw[cin][k][cout]
        for (int i = t; i < 9216; i += 256) {
            int cout = i / 72;
            int r = i - cout * 72;      // cin*9 + k
            int ci = r / 9;
            int k = r - ci * 9;
            sw[ci * 1260 + k * 140 + cout] = cw[cout * 576 + (ci0 + ci) * 9 + k];
        }
        __syncthreads();

#pragma unroll
        for (int ci = 0; ci < 8; ++ci) {
#pragma unroll
            for (int kh = 0; kh < 3; ++kh) {
                const float* xr = &sx[kh * 544 + ci * 68 + w0];
                float4 a4 = *(const float4*)xr;
                float2 a2 = *(const float2*)(xr + 4);
                float xv[6] = {a4.x, a4.y, a4.z, a4.w, a2.x, a2.y};
#pragma unroll
                for (int kw = 0; kw < 3; ++kw) {
                    const float* wr = &sw[ci * 1260 + (kh * 3 + kw) * 140 + co8];
                    float4 wA = *(const float4*)wr;
                    float4 wB = *(const float4*)(wr + 4);
                    float wv[8] = {wA.x, wA.y, wA.z, wA.w, wB.x, wB.y, wB.z, wB.w};
#pragma unroll
                    for (int i = 0; i < 8; i++)
#pragma unroll
                        for (int j = 0; j < 4; j++)
                            acc[i][j] = fmaf(wv[i], xv[kw + j], acc[i][j]);
                }
            }
        }
        __syncthreads();
    }

    // store raw conv output
    size_t obase = ((size_t)(b * NCO) * NH + h) * NW;
    float s1l[8], s2l[8];
#pragma unroll
    for (int i = 0; i < 8; i++) {
        float4 v;
        v.x = acc[i][0]; v.y = acc[i][1]; v.z = acc[i][2]; v.w = acc[i][3];
        *(float4*)&g_hraw[obase + (size_t)(co8 + i) * (NH * NW) + w0] = v;
        s1l[i] = acc[i][0] + acc[i][1] + acc[i][2] + acc[i][3];
        s2l[i] = acc[i][0]*acc[i][0] + acc[i][1]*acc[i][1] +
                 acc[i][2]*acc[i][2] + acc[i][3]*acc[i][3];
    }
    // per-channel block reduction for BN1 stats (reuse sw)
    float* red = sw;   // needs 4096 floats
    int wg = t & 15;
#pragma unroll
    for (int i = 0; i < 8; i++) {
        red[(co8 + i) * 16 + wg] = s1l[i];
        red[2048 + (co8 + i) * 16 + wg] = s2l[i];
    }
    __syncthreads();
    if (t < 128) {
        float a = 0.f, c2 = 0.f;
#pragma unroll
        for (int g = 0; g < 16; g++) { a += red[t * 16 + g]; c2 += red[2048 + t * 16 + g]; }
        atomicAdd(&g_s1[t], a);
        atomicAdd(&g_s2[t], c2);
    }
}

// ---------------- 2: finalize BN1 scale/shift -------------------------------
__global__ void k_bn1fin(const float* __restrict__ g1, const float* __restrict__ b1) {
    int c = threadIdx.x;
    if (c < NCO) {
        float mean = g_s1[c] * (1.f / NHW_F);
        float var  = g_s2[c] * (1.f / NHW_F) - mean * mean;
        float a = g1[c] * rsqrtf(var + CEPS);
        g_a1[c] = a;
        g_b1v[c] = b1[c] - mean * a;
    }
}

// ---------------- 3: apply BN1+ReLU, row means over W, Σh/Σh² partials ------
// grid: 2048 = (b,c). 256 threads = 8 warps, warp owns one h row per iter.
__global__ void __launch_bounds__(256) k_bnrelu_xm() {
    int bc = blockIdx.x;
    int c = bc & 127;
    int t = threadIdx.x, lane = t & 31, wid = t >> 5;
    float a1 = g_a1[c], b1 = g_b1v[c];
    const float2* src = (const float2*)(g_hraw + (size_t)bc * NH * NW);
    float p1 = 0.f, p2 = 0.f;
    for (int it = 0; it < 64; ++it) {
        int h = it * 8 + wid;
        float2 v = src[h * 32 + lane];
        float v0 = fmaxf(fmaf(v.x, a1, b1), 0.f);
        float v1 = fmaxf(fmaf(v.y, a1, b1), 0.f);
        float s = v0 + v1;
        p1 += s;
        p2 += v0 * v0 + v1 * v1;
        s = warpsum(s);
        if (lane == 0) g_xm[(size_t)bc * NH + h] = s * (1.f / 64.f);
    }
    __shared__ float r1[8], r2[8];
    p1 = warpsum(p1); p2 = warpsum(p2);
    if (lane == 0) { r1[wid] = p1; r2[wid] = p2; }
    __syncthreads();
    if (t == 0) {
        float a = 0.f, b2 = 0.f;
#pragma unroll
        for (int i = 0; i < 8; i++) { a += r1[i]; b2 += r2[i]; }
        g_p1[bc] = a; g_p2[bc] = b2;
    }
}

// ---------------- 4: layernorm over (C,H) per batch -------------------------
__global__ void __launch_bounds__(256) k_ln() {
    int b = blockIdx.x;
    const float* xm = g_xm + b * (NCO * NH);
    float* xn = g_xn + b * (NCO * NH);
    int t = threadIdx.x, lane = t & 31, wid = t >> 5;
    float s = 0.f, s2 = 0.f;
    for (int i = t; i < NCO * NH; i += 256) { float v = xm[i]; s += v; s2 += v * v; }
    __shared__ float rb[16];
    __shared__ float st[2];
    s = warpsum(s); s2 = warpsum(s2);
    if (lane == 0) { rb[wid] = s; rb[8 + wid] = s2; }
    __syncthreads();
    if (t == 0) {
        float a = 0.f, b2 = 0.f;
#pragma unroll
        for (int i = 0; i < 8; i++) { a += rb[i]; b2 += rb[8 + i]; }
        float mu = a * (1.f / 65536.f);
        float var = b2 * (1.f / 65536.f) - mu * mu;
        st[0] = mu; st[1] = rsqrtf(var + CEPS);
    }
    __syncthreads();
    float mu = st[0], rs = st[1];
    for (int i = t; i < NCO * NH; i += 256) xn[i] = (xm[i] - mu) * rs;
}

// ---------------- 5: Wc = out_w @ g_w (stored transposed), bc = out_w @ g_b -
__global__ void k_wc(const float* __restrict__ ow, const float* __restrict__ gw,
                     const float* __restrict__ gb) {
    int o = blockIdx.x, c = threadIdx.x;
    float s = 0.f;
    for (int m = 0; m < NCO; m++) s = fmaf(ow[o * NCO + m], gw[m * NCO + c], s);
    g_wct[c * NCO + o] = s;
    if (c == 0) {
        float bb = 0.f;
        for (int m = 0; m < NCO; m++) bb = fmaf(ow[o * NCO + m], gb[m], bb);
        g_bcv[o] = bb;
    }
}

// ---------------- 6: z[b,o,k] = Σc Wc[o,c]*xn[b,c,k] + bc[o] ----------------
// grid: (8 ktiles, 16 b). xn tile in smem, WcT rows via L1 (uniform float4 LDG)
__global__ void __launch_bounds__(256) k_z() {
    __shared__ float xs[NCO * 64];
    int k0 = blockIdx.x * 64, b = blockIdx.y;
    int t = threadIdx.x;
    for (int i = t; i < NCO * 64; i += 256) {
        int c = i >> 6, kk = i & 63;
        xs[i] = g_xn[((b << 7) + c) * NH + k0 + kk];
    }
    __syncthreads();
    int kk = t & 63, og = t >> 6;      // og: 0..3 -> 32 couts each
    float acc[32];
#pragma unroll
    for (int i = 0; i < 32; i++) acc[i] = 0.f;
    for (int c = 0; c < NCO; c++) {
        float xv = xs[c * 64 + kk];
        const float4* wr = (const float4*)(g_wct + c * NCO + og * 32);
#pragma unroll
        for (int i4 = 0; i4 < 8; i4++) {
            float4 wv = __ldg(wr + i4);
            acc[i4 * 4 + 0] = fmaf(wv.x, xv, acc[i4 * 4 + 0]);
            acc[i4 * 4 + 1] = fmaf(wv.y, xv, acc[i4 * 4 + 1]);
            acc[i4 * 4 + 2] = fmaf(wv.z, xv, acc[i4 * 4 + 2]);
            acc[i4 * 4 + 3] = fmaf(wv.w, xv, acc[i4 * 4 + 3]);
        }
    }
#pragma unroll
    for (int i = 0; i < 32; i++) {
        int o = og * 32 + i;
        g_zz[((b << 7) + o) * NH + k0 + kk] = acc[i] + g_bcv[o];
    }
}

// ---------------- 7: S = xn^T xn / sqrt(C)  [b,h,k] -------------------------
// grid: (8 kt, 8 ht, 16 b). 64x64 tile, two 64-c chunks.
__global__ void __launch_bounds__(256) k_sgemm() {
    __shared__ float As[64 * 64], Bs[64 * 64];
    int k0 = blockIdx.x * 64, h0 = blockIdx.y * 64, b = blockIdx.z;
    int t = threadIdx.x, tx = t & 15, ty = t >> 4;
    float acc[4][4];
#pragma unroll
    for (int i = 0; i < 4; i++)
#pragma unroll
        for (int j = 0; j < 4; j++) acc[i][j] = 0.f;
    for (int cc = 0; cc < 2; ++cc) {
        int c0 = cc * 64;
        for (int i = t; i < 4096; i += 256) {
            int c = i >> 6, j = i & 63;
            As[i] = g_xn[((b << 7) + c0 + c) * NH + h0 + j];
            Bs[i] = g_xn[((b << 7) + c0 + c) * NH + k0 + j];
        }
        __syncthreads();
#pragma unroll 8
        for (int c = 0; c < 64; c++) {
            float4 av = *(const float4*)&As[c * 64 + ty * 4];
            float4 bv = *(const float4*)&Bs[c * 64 + tx * 4];
            float a[4] = {av.x, av.y, av.z, av.w};
            float bb[4] = {bv.x, bv.y, bv.z, bv.w};
#pragma unroll
            for (int i = 0; i < 4; i++)
#pragma unroll
                for (int j = 0; j < 4; j++) acc[i][j] = fmaf(a[i], bb[j], acc[i][j]);
        }
        __syncthreads();
    }
    const float SC = 0.08838834764831845f;  // 1/sqrt(128)
#pragma unroll
    for (int i = 0; i < 4; i++) {
        float4 v;
        v.x = acc[i][0] * SC; v.y = acc[i][1] * SC;
        v.z = acc[i][2] * SC; v.w = acc[i][3] * SC;
        *(float4*)&g_f[((size_t)(b << 9) + h0 + ty * 4 + i) * NH + k0 + tx * 4] = v;
    }
}

// ---------------- 8: row softmax over k (512) -------------------------------
__global__ void __launch_bounds__(128) k_softmax() {
    size_t row = blockIdx.x;
    float4* p = (float4*)(g_f + row * NH);
    int t = threadIdx.x, lane = t & 31, wid = t >> 5;
    __shared__ float sb[4];
    float4 v = p[t];
    float m = fmaxf(fmaxf(v.x, v.y), fmaxf(v.z, v.w));
    m = warpmax(m);
    if (lane == 0) sb[wid] = m;
    __syncthreads();
    m = fmaxf(fmaxf(sb[0], sb[1]), fmaxf(sb[2], sb[3]));
    float e0 = expf(v.x - m), e1 = expf(v.y - m), e2 = expf(v.z - m), e3 = expf(v.w - m);
    float s = e0 + e1 + e2 + e3;
    s = warpsum(s);
    __syncthreads();
    if (lane == 0) sb[wid] = s;
    __syncthreads();
    float inv = 1.f / (sb[0] + sb[1] + sb[2] + sb[3]);
    float4 o; o.x = e0 * inv; o.y = e1 * inv; o.z = e2 * inv; o.w = e3 * inv;
    p[t] = o;
}

// ---------------- 9: y3[b,o,h] = Σk f[b,h,k] z[b,o,k] + out_b[o] ------------
// grid: (8 ht, 16 b). k in chunks of 32. thread: 4h x 8o.
__global__ void __launch_bounds__(256) k_y3(const float* __restrict__ outb) {
    __shared__ float fs[64 * 35];     // [hh][kk], pad 35
    __shared__ float zs[NCO * 32];    // [o][kk]
    int h0 = blockIdx.x * 64, b = blockIdx.y;
    int t = threadIdx.x, hx = t & 15, og = t >> 4;
    float acc[4][8];
#pragma unroll
    for (int j = 0; j < 4; j++)
#pragma unroll
        for (int i = 0; i < 8; i++) acc[j][i] = 0.f;
    for (int kt = 0; kt < 16; ++kt) {
        int k0 = kt * 32;
        for (int i = t; i < 2048; i += 256) {
            int hh = i >> 5, kk = i & 31;
            fs[hh * 35 + kk] = g_f[((size_t)(b << 9) + h0 + hh) * NH + k0 + kk];
        }
        for (int i = t; i < 4096; i += 256) {
            int o = i >> 5, kk = i & 31;
            zs[i] = g_zz[((b << 7) + o) * NH + k0 + kk];
        }
        __syncthreads();
#pragma unroll 4
        for (int kk = 0; kk < 32; kk++) {
            float fv[4], zv[8];
#pragma unroll
            for (int j = 0; j < 4; j++) fv[j] = fs[(hx * 4 + j) * 35 + kk];
#pragma unroll
            for (int i = 0; i < 8; i++) zv[i] = zs[(og * 8 + i) * 32 + kk];
#pragma unroll
            for (int j = 0; j < 4; j++)
#pragma unroll
                for (int i = 0; i < 8; i++) acc[j][i] = fmaf(fv[j], zv[i], acc[j][i]);
        }
        __syncthreads();
    }
#pragma unroll
    for (int i = 0; i < 8; i++) {
        int o = og * 8 + i;
        float ob = outb[o];
#pragma unroll
        for (int j = 0; j < 4; j++)
            g_y3[((b << 7) + o) * NH + h0 + hx * 4 + j] = acc[j][i] + ob;
    }
}

// ---------------- 10: BN2 stats from small tensors --------------------------
// Σ(h+y) = Σh + 64Σy ;  Σ(h+y)² = Σh² + 128Σ(y·xm) + 64Σy²   (Σ_w h = 64·xm)
__global__ void __launch_bounds__(256) k_bn2red(const float* __restrict__ g2,
                                                const float* __restrict__ b2p) {
    int c = blockIdx.x;
    int t = threadIdx.x, lane = t & 31, wid = t >> 5;
    float sy = 0.f, sy2 = 0.f, sxy = 0.f;
    for (int i = t; i < NB * NH; i += 256) {
        int b = i >> 9, h = i & 511;
        size_t idx = (size_t)((b << 7) + c) * NH + h;
        float y = g_y3[idx], xm = g_xm[idx];
        sy += y; sy2 += y * y; sxy += y * xm;
    }
    float sp1 = 0.f, sp2 = 0.f;
    if (t < NB) { sp1 = g_p1[t * NCO + c]; sp2 = g_p2[t * NCO + c]; }
    __shared__ float rb[5][8];
    sy = warpsum(sy); sy2 = warpsum(sy2); sxy = warpsum(sxy);
    sp1 = warpsum(sp1); sp2 = warpsum(sp2);
    if (lane == 0) { rb[0][wid]=sy; rb[1][wid]=sy2; rb[2][wid]=sxy; rb[3][wid]=sp1; rb[4][wid]=sp2; }
    __syncthreads();
    if (t == 0) {
        float SY=0, SY2=0, SXY=0, P1=0, P2=0;
#pragma unroll
        for (int i = 0; i < 8; i++) { SY+=rb[0][i]; SY2+=rb[1][i]; SXY+=rb[2][i]; P1+=rb[3][i]; P2+=rb[4][i]; }
        float S1 = P1 + 64.f * SY;
        float S2 = P2 + 128.f * SXY + 64.f * SY2;
        float mean = S1 * (1.f / NHW_F);
        float var  = S2 * (1.f / NHW_F) - mean * mean;
        float a = g2[c] * rsqrtf(var + CEPS);
        g_a2[c] = a;
        g_b2v[c] = b2p[c] - mean * a;
    }
}

// ---------------- 11: fused epilogue: BN1+ReLU + add y + BN2 + SiLU ---------
__global__ void __launch_bounds__(256) k_final(float* __restrict__ out) {
    size_t gi = (size_t)blockIdx.x * 256 + threadIdx.x;   // float4 index
    size_t base = gi * 4;
    size_t row = base >> 6;                               // (b*128+c)*512+h
    int c = (int)((row >> 9) & 127);
    float a1 = g_a1[c], b1 = g_b1v[c], a2 = g_a2[c], b2 = g_b2v[c];
    float yv = g_y3[row];
    float4 v = *(const float4*)(g_hraw + base);
    float q, r[4], in[4] = {v.x, v.y, v.z, v.w};
#pragma unroll
    for (int i = 0; i < 4; i++) {
        float hp = fmaxf(fmaf(in[i], a1, b1), 0.f);
        q = fmaf(hp + yv, a2, b2);
        r[i] = q * (1.f / (1.f + expf(-q)));
    }
    float4 o; o.x = r[0]; o.y = r[1]; o.z = r[2]; o.w = r[3];
    *(float4*)(out + base) = o;
}

// ---------------- launch ----------------------------------------------------
extern "C" void kernel_launch(void* const* d_in, const int* in_sizes, int n_in,
                              void* d_out, int out_size) {
    const float* x      = (const float*)d_in[0];
    const float* conv_w = (const float*)d_in[1];
    const float* bn1_g  = (const float*)d_in[2];
    const float* bn1_b  = (const float*)d_in[3];
    const float* gw     = (const float*)d_in[4];
    const float* gb     = (const float*)d_in[5];
    const float* ow     = (const float*)d_in[6];
    const float* ob     = (const float*)d_in[7];
    const float* bn2_g  = (const float*)d_in[8];
    const float* bn2_b  = (const float*)d_in[9];
    float* out = (float*)d_out;

    k_zero<<<1, 256>>>();
    k_conv<<<NB * NH, 256>>>(x, conv_w);
    k_bn1fin<<<1, 128>>>(bn1_g, bn1_b);
    k_bnrelu_xm<<<NB * NCO, 256>>>();
    k_ln<<<NB, 256>>>();
    k_wc<<<NCO, NCO>>>(ow, gw, gb);
    k_z<<<dim3(8, NB), 256>>>();
    k_sgemm<<<dim3(8, 8, NB), 256>>>();
    k_softmax<<<NB * NH, 128>>>();
    k_y3<<<dim3(8, NB), 256>>>(ob);
    k_bn2red<<<NCO, 256>>>(bn2_g, bn2_b);
    k_final<<<65536, 256>>>(out);
}